// round 7
// baseline (speedup 1.0000x reference)
#include <cuda_runtime.h>
#include <cub/cub.cuh>

#define CH 256
#define SC 16
#define HC 8
#define SSPAN (SC*CH)
#define HSPAN (HC*SC*CH)
constexpr int MAXN = 1 << 18;
constexpr int MAXC = MAXN / CH;
constexpr int MAXS = MAXC / SC;
constexpr int MAXH = MAXS / HC;
constexpr int CAP  = 6400;
constexpr int NCK  = 512;
constexpr int DIP_DYN = CAP*16*2 + 1024*8 + 1024*4 + NCK*8;   // 221184
constexpr int LVL2_DYN = 6400*32;                              // 204800

__device__ float  g_proj[MAXN];
__device__ float  g_sorted[MAXN];
__device__ int    g_lh_idx[MAXN];  __device__ double g_lh_val[MAXN];  __device__ int g_lhn[MAXC];
__device__ int    g_uh_idx[MAXN];  __device__ double g_uh_val[MAXN];  __device__ int g_uhn[MAXC];
__device__ int    g_slh_idx[MAXN]; __device__ double g_slh_val[MAXN]; __device__ int g_slhn[MAXS];
__device__ int    g_suh_idx[MAXN]; __device__ double g_suh_val[MAXN]; __device__ int g_suhn[MAXS];
__device__ int    g_hlh_idx[MAXN]; __device__ double g_hlh_val[MAXN]; __device__ int g_hlhn[MAXH];
__device__ int    g_huh_idx[MAXN]; __device__ double g_huh_val[MAXN]; __device__ int g_huhn[MAXH];
__device__ int    g_Hidx[MAXN + 2]; __device__ double g_Hval[MAXN + 2]; __device__ float g_Hv32[MAXN + 2];
__device__ int    g_Sidx[MAXN + 2]; __device__ double g_Sval[MAXN + 2]; __device__ float g_Sv32[MAXN + 2];
__device__ unsigned char g_cub_tmp[1 << 24];

__global__ void k_matvec(const float* __restrict__ X, const float* __restrict__ PV,
                         const int* __restrict__ IDX, int N) {
    __shared__ __align__(16) float sp[128];
    int pidx = IDX[0];
    if (threadIdx.x < 128) sp[threadIdx.x] = PV[pidx * 128 + threadIdx.x];
    __syncthreads();
    int g = blockIdx.x * blockDim.x + threadIdx.x;
    int row = g >> 5, lane = g & 31;
    if (row >= N) return;
    const float4* xr = reinterpret_cast<const float4*>(X) + (size_t)row * 32;
    float4 a = xr[lane];
    float4 b = reinterpret_cast<const float4*>(sp)[lane];
    float s = a.x * b.x + a.y * b.y + a.z * b.z + a.w * b.w;
#pragma unroll
    for (int o = 16; o; o >>= 1) s += __shfl_xor_sync(0xffffffffu, s, o);
    if (lane == 0) g_proj[row] = s;
}

// f32-filtered strict monotone chain; exact reference f64 compare on ambiguity.
__device__ __forceinline__ int merge_f32_resume(int* idx, double* val, float* v32,
                                                int m0, int end) {
    int m = m0, ai = 0, bi = 0; double av = 0.0, bv = 0.0; float af = 0.f, bf = 0.f;
    if (m >= 1) { bi = idx[m-1]; bv = val[m-1]; bf = v32[m-1]; }
    if (m >= 2) { ai = idx[m-2]; av = val[m-2]; af = v32[m-2]; }
    for (int r = m0; r < end; r++) {
        int ci = idx[r]; double cv = val[r]; float cf = v32[r];
        while (m >= 2) {
            float p1 = (cf - bf) * (float)(bi - ai);
            float p2 = (bf - af) * (float)(ci - bi);
            float eps = 4e-7f * (fabsf(p1) + fabsf(p2)) + 1e-33f;
            float diff = p1 - p2;
            bool brk;
            if (diff < -eps) brk = true;
            else if (diff > eps) brk = false;
            else brk = ((cv - bv) * (double)(bi - ai)) < ((bv - av) * (double)(ci - bi));
            if (brk) break;
            m--; bi = ai; bv = av; bf = af;
            if (m >= 2) { ai = idx[m - 2]; av = val[m - 2]; af = v32[m - 2]; }
        }
        idx[m] = ci; val[m] = cv; v32[m] = cf;
        ai = bi; av = bv; af = bf; bi = ci; bv = cv; bf = cf; m++;
    }
    return m;
}
__device__ __forceinline__ int merge_f64(int* idx, double* val, int n) {
    int m = 0, ai = 0, bi = 0; double av = 0.0, bv = 0.0;
    for (int r = 0; r < n; r++) {
        int ci = idx[r]; double cv = val[r];
        while (m >= 2) {
            if ((cv - bv) * (double)(bi - ai) < (bv - av) * (double)(ci - bi)) break;
            m--; bi = ai; bv = av;
            if (m >= 2) { ai = idx[m - 2]; av = val[m - 2]; }
        }
        idx[m] = ci; val[m] = cv;
        ai = bi; av = bv; bi = ci; bv = cv; m++;
    }
    return m;
}

__global__ void k_chunk_hulls(int N) {
    __shared__ int iL[CH]; __shared__ double vL[CH]; __shared__ float fL[CH];
    __shared__ int iU[CH]; __shared__ double vU[CH]; __shared__ float fU[CH];
    __shared__ int smL, smU;
    int c = blockIdx.x, tid = threadIdx.x;
    int s = c * CH + 1, e = min((c + 1) * CH, N), n = e - s + 1;
    for (int k = tid; k < n; k += blockDim.x) {
        float x = g_sorted[s + k - 1];
        iL[k] = s + k;         vL[k] = (double)x;         fL[k] = x;
        iU[n - 1 - k] = s + k; vU[n - 1 - k] = (double)x; fU[n - 1 - k] = x;
    }
    __syncthreads();
    if (tid == 0)  smL = merge_f32_resume(iL, vL, fL, 0, n);
    if (tid == 64) smU = merge_f32_resume(iU, vU, fU, 0, n);
    __syncthreads();
    int base = c * CH;
    for (int k = tid; k < smL; k += blockDim.x) { g_lh_idx[base+k] = iL[k]; g_lh_val[base+k] = vL[k]; }
    for (int k = tid; k < smU; k += blockDim.x) { g_uh_idx[base+k] = iU[k]; g_uh_val[base+k] = vU[k]; }
    if (tid == 0)  g_lhn[c] = smL;
    if (tid == 64) g_uhn[c] = smU;
}

__global__ void k_level(const int* sLi, const double* sLv, const int* sLn,
                        int* dLi, double* dLv, int* dLn,
                        const int* sUi, const double* sUv, const int* sUn,
                        int* dUi, double* dUv, int* dUn,
                        int group, int srcStride, int dstStride, int nsrc, int cap) {
    extern __shared__ unsigned char sm[];
    double* vL = (double*)sm;
    double* vU = vL + cap;
    float*  fL = (float*)(vU + cap);
    float*  fU = fL + cap;
    int*    iL = (int*)(fU + cap);
    int*    iU = iL + cap;
    __shared__ int offL[24], offU[24];
    __shared__ int totL, totU, mL, mU, fbL, fbU;
    int b = blockIdx.x, tid = threadIdx.x;
    int j0 = b * group, j1 = min(j0 + group, nsrc), nj = j1 - j0;
    if (tid == 0)  { int o = 0; for (int j = j0; j < j1; j++) { offL[j-j0] = o; o += sLn[j]; } totL = o; fbL = (o > cap); }
    if (tid == 32) { int o = 0; for (int j = j1-1; j >= j0; j--) { offU[j1-1-j] = o; o += sUn[j]; } totU = o; fbU = (o > cap); }
    __syncthreads();
    size_t db = (size_t)b * dstStride;
    for (int j = 0; j < nj; j++) {
        int src = (j0+j)*srcStride, len = sLn[j0+j], dst = offL[j];
        if (!fbL) for (int k = tid; k < len; k += blockDim.x) { iL[dst+k] = sLi[src+k]; double v = sLv[src+k]; vL[dst+k] = v; fL[dst+k] = (float)v; }
        else      for (int k = tid; k < len; k += blockDim.x) { dLi[db+dst+k] = sLi[src+k]; dLv[db+dst+k] = sLv[src+k]; }
        int ju = j1-1-j, srcu = ju*srcStride, lenu = sUn[ju], dstu = offU[j];
        if (!fbU) for (int k = tid; k < lenu; k += blockDim.x) { iU[dstu+k] = sUi[srcu+k]; double v = sUv[srcu+k]; vU[dstu+k] = v; fU[dstu+k] = (float)v; }
        else      for (int k = tid; k < lenu; k += blockDim.x) { dUi[db+dstu+k] = sUi[srcu+k]; dUv[db+dstu+k] = sUv[srcu+k]; }
    }
    __syncthreads();
    if (tid == 0)  mL = fbL ? merge_f64(dLi+db, dLv+db, totL) : merge_f32_resume(iL, vL, fL, 0, totL);
    if (tid == 32) mU = fbU ? merge_f64(dUi+db, dUv+db, totU) : merge_f32_resume(iU, vU, fU, 0, totU);
    __syncthreads();
    if (!fbL) for (int k = tid; k < mL; k += blockDim.x) { dLi[db+k] = iL[k]; dLv[db+k] = vL[k]; }
    if (!fbU) for (int k = tid; k < mU; k += blockDim.x) { dUi[db+k] = iU[k]; dUv[db+k] = vU[k]; }
    if (tid == 0)  dLn[b] = mL;
    if (tid == 32) dUn[b] = mU;
}

// interval candidate source builders (hierarchy decomposition)
__device__ int buildSrcL(int a, int b, int4* src, int N) {
    int ns = 0;
    while (a <= b) {
        int h = (a-1)/HSPAN, hs = h*HSPAN+1, he = min(hs+HSPAN-1, N);
        int s = (a-1)/SSPAN, ss = s*SSPAN+1, se = min(ss+SSPAN-1, N);
        int c = (a-1)/CH,    cs = c*CH+1,    ce = min(cs+CH-1, N);
        if (a == hs && he <= b)      { src[ns++] = make_int4(6, h*HSPAN, g_hlhn[h], 0); a = he + 1; }
        else if (a == ss && se <= b) { src[ns++] = make_int4(1, s*SSPAN, g_slhn[s], 0); a = se + 1; }
        else if (a == cs && ce <= b) { src[ns++] = make_int4(0, c*CH,    g_lhn[c],  0); a = ce + 1; }
        else { int e2 = min(b, ce); src[ns++] = make_int4(2, a, e2 - a + 1, 0); a = e2 + 1; }
    }
    return ns;
}
__device__ int buildSrcU(int a, int b, int4* src, int N) {
    int ns = 0;
    while (b >= a) {
        int h = (b-1)/HSPAN, hs = h*HSPAN+1, he = min(hs+HSPAN-1, N);
        int s = (b-1)/SSPAN, ss = s*SSPAN+1, se = min(ss+SSPAN-1, N);
        int c = (b-1)/CH,    cs = c*CH+1,    ce = min(cs+CH-1, N);
        if (b == he && hs >= a)      { src[ns++] = make_int4(7, h*HSPAN, g_huhn[h], 0); b = hs - 1; }
        else if (b == se && ss >= a) { src[ns++] = make_int4(4, s*SSPAN, g_suhn[s], 0); b = ss - 1; }
        else if (b == ce && cs >= a) { src[ns++] = make_int4(3, c*CH,    g_uhn[c],  0); b = cs - 1; }
        else { int s2 = max(a, cs); src[ns++] = make_int4(5, b, b - s2 + 1, 0); b = s2 - 1; }
    }
    return ns;
}

__global__ void __launch_bounds__(1024, 1) k_dip(int N, float* out) {
    extern __shared__ unsigned char dyn[];
    double* dValL = (double*)dyn;                 // CAP
    double* dValU = dValL + CAP;                  // CAP
    double* red   = dValU + CAP;                  // 1024
    float*  dF32L = (float*)(red + 1024);         // CAP
    float*  dF32U = dF32L + CAP;                  // CAP
    int*    dIdxL = (int*)(dF32U + CAP);          // CAP
    int*    dIdxU = dIdxL + CAP;                  // CAP
    unsigned* meta = (unsigned*)(dIdxU + CAP);    // 1024
    int2*   ckpt = (int2*)(meta + 1024);          // NCK

    __shared__ int s_low, s_high, s_done, s_glL, s_glU, s_migL, s_migU;
    __shared__ double s_dip;
    __shared__ int nsL, nsU, totL, totU, s_mL, s_mU, s_lg, s_ll, s_ig, s_ih;
    __shared__ int s_pbL, s_pbU, s_S, s_seq;
    __shared__ int4 srcL[64], srcU[64];
    __shared__ int* pIL; __shared__ double* pVL; __shared__ float* pFL;
    __shared__ int* pIU; __shared__ double* pVU; __shared__ float* pFU;

    int tid = threadIdx.x;
    if (tid == 0) {
        s_low = 1; s_high = N; s_dip = 1.0; s_done = 0; s_glL = 0; s_glU = 0;
        s_mL = 0; s_mU = 0;
        pIL = dIdxL; pVL = dValL; pFL = dF32L;
        pIU = dIdxU; pVU = dValU; pFU = dF32U;
    }
    __syncthreads();
    if (N < 4 || g_sorted[0] == g_sorted[N - 1]) {
        if (tid == 0) out[0] = (float)(1.0 / (2.0 * (double)(N > 0 ? N : 1)));
        return;
    }

    for (int iter = 0; iter < 64; iter++) {
        int low = s_low, high = s_high;

        // ---- planning: truncation cache + gap candidates ----
        if (tid == 0) {
            int pbase = 0, a = 1;
            if (iter > 0) {
                int lo = 0, hi = s_mL - 1;
                while (lo < hi) { int mid = (lo+hi+1)>>1; if (pIL[mid] <= high) lo = mid; else hi = mid-1; }
                if (pIL[lo] == high) { s_mL = lo + 1; pbase = -1; }
                else { pbase = lo + 1; a = pIL[lo] + 1; }
            }
            s_pbL = pbase; s_migL = 0; nsL = 0; totL = 0;
            if (pbase >= 0) {
                int ns = buildSrcL(a, high, srcL, N);
                int o = 0;
                for (int j = 0; j < ns; j++) { srcL[j].w = o; o += srcL[j].z; }
                nsL = ns; totL = o;
                if (!s_glL && pbase + o > CAP) s_migL = 1;
            }
        }
        if (tid == 32) {
            int pbase = 0, b = N;
            if (iter > 0) {
                int lo = 0, hi = s_mU - 1;
                while (lo < hi) { int mid = (lo+hi+1)>>1; if (pIU[mid] >= low) lo = mid; else hi = mid-1; }
                if (pIU[lo] == low) { s_mU = lo + 1; pbase = -1; }
                else { pbase = lo + 1; b = pIU[lo] - 1; }
            }
            s_pbU = pbase; s_migU = 0; nsU = 0; totU = 0;
            if (pbase >= 0) {
                int ns = buildSrcU(low, b, srcU, N);
                int o = 0;
                for (int j = 0; j < ns; j++) { srcU[j].w = o; o += srcU[j].z; }
                nsU = ns; totU = o;
                if (!s_glU && pbase + o > CAP) s_migU = 1;
            }
        }
        __syncthreads();

        // ---- migration to global on overflow (sticky) ----
        if (s_migL) for (int k = tid; k < s_pbL; k += 1024) { g_Hidx[k] = dIdxL[k]; g_Hval[k] = dValL[k]; g_Hv32[k] = dF32L[k]; }
        if (s_migU) for (int k = tid; k < s_pbU; k += 1024) { g_Sidx[k] = dIdxU[k]; g_Sval[k] = dValU[k]; g_Sv32[k] = dF32U[k]; }
        __syncthreads();
        if (tid == 0 && s_migL)  { pIL = g_Hidx; pVL = g_Hval; pFL = g_Hv32; s_glL = 1; }
        if (tid == 32 && s_migU) { pIU = g_Sidx; pVU = g_Sval; pFU = g_Sv32; s_glU = 1; }
        __syncthreads();

        // ---- stage gap candidates ----
        if (s_pbL >= 0) {
            int* IL = pIL; double* VL = pVL; float* FL = pFL; int pb = s_pbL;
            for (int j = 0; j < nsL; j++) {
                int4 sd = srcL[j];
                if (sd.x == 2) {
                    for (int k = tid; k < sd.z; k += 1024) {
                        float x = g_sorted[sd.y + k - 1];
                        IL[pb+sd.w+k] = sd.y + k; VL[pb+sd.w+k] = (double)x; FL[pb+sd.w+k] = x;
                    }
                } else {
                    const int* si; const double* sv;
                    if (sd.x == 0)      { si = g_lh_idx;  sv = g_lh_val; }
                    else if (sd.x == 1) { si = g_slh_idx; sv = g_slh_val; }
                    else                { si = g_hlh_idx; sv = g_hlh_val; }
                    for (int k = tid; k < sd.z; k += 1024) {
                        double v = sv[sd.y + k];
                        IL[pb+sd.w+k] = si[sd.y + k]; VL[pb+sd.w+k] = v; FL[pb+sd.w+k] = (float)v;
                    }
                }
            }
        }
        if (s_pbU >= 0) {
            int* IU = pIU; double* VU = pVU; float* FU = pFU; int pb = s_pbU;
            for (int j = 0; j < nsU; j++) {
                int4 sd = srcU[j];
                if (sd.x == 5) {
                    for (int k = tid; k < sd.z; k += 1024) {
                        float x = g_sorted[sd.y - k - 1];
                        IU[pb+sd.w+k] = sd.y - k; VU[pb+sd.w+k] = (double)x; FU[pb+sd.w+k] = x;
                    }
                } else {
                    const int* si; const double* sv;
                    if (sd.x == 3)      { si = g_uh_idx;  sv = g_uh_val; }
                    else if (sd.x == 4) { si = g_suh_idx; sv = g_suh_val; }
                    else                { si = g_huh_idx; sv = g_huh_val; }
                    for (int k = tid; k < sd.z; k += 1024) {
                        double v = sv[sd.y + k];
                        IU[pb+sd.w+k] = si[sd.y + k]; VU[pb+sd.w+k] = v; FU[pb+sd.w+k] = (float)v;
                    }
                }
            }
        }
        __syncthreads();

        // ---- merges (resume from preserved prefix) + window truncation ----
        if (tid == 0) {
            if (s_pbL >= 0) s_mL = merge_f32_resume(pIL, pVL, pFL, s_pbL, s_pbL + totL);
            int m = s_mL;
            int lo = 0, hi = m - 1;
            while (lo < hi) { int mid = (lo+hi+1)>>1; if (pIL[mid] <= low) lo = mid; else hi = mid-1; }
            s_lg = m - lo;
        }
        if (tid == 32) {
            if (s_pbU >= 0) s_mU = merge_f32_resume(pIU, pVU, pFU, s_pbU, s_pbU + totU);
            int m = s_mU;
            int lo = 0, hi = m - 1;
            while (lo < hi) { int mid = (lo+hi+1)>>1; if (pIU[mid] >= high) lo = mid; else hi = mid-1; }
            s_ll = m - lo;
        }
        __syncthreads();

        int mL = s_mL, mU = s_mU, lg = s_lg, ll = s_ll;

        // ---- d-walk phase 1: integer-only path walk + checkpoints ----
        if (tid == 0) {
            s_seq = 0;
            if (lg == 2 && ll == 2) { s_S = -1; }     // special: d = 1.0
            else {
                int ix = lg - 1, iv = 2, S = 0;
                long long guard = 4LL * N + 16;
                while (guard-- > 0) {
                    if ((S & 31) == 0 && (S >> 5) < NCK) ckpt[S >> 5] = make_int2(ix, iv);
                    if (pIL[mL-ix] > pIU[mU-iv]) iv++; else ix--;
                    if (ix < 1) ix = 1;
                    if (iv > ll) iv = ll;
                    S++;
                    if (pIL[mL-ix] == pIU[mU-iv]) break;
                }
                s_S = S;
                if (S > NCK * 32 || s_glL || s_glU) s_seq = 1;
            }
        }
        __syncthreads();

        if (s_S == -1) {
            if (tid == 0) { s_ig = lg; s_ih = ll; if (1.0 < s_dip) s_done = 1; }
        } else if (s_seq) {
            if (tid == 0) {      // rare fallback: sequential reference walk
                int ig = lg, ih = ll, ix = lg - 1, iv = 2;
                double d = 0.0;
                long long guard = 4LL * N + 16;
                while (guard-- > 0) {
                    int gcmix = pIL[mL-ix], lcmiv = pIU[mU-iv];
                    if (gcmix > lcmiv) {
                        int gcmi1 = pIL[mL-ix-1];
                        double t = (double)(lcmiv - gcmi1 + 1)
                                 - (pVU[mU-iv] - pVL[mL-ix-1]) * (double)(gcmix - gcmi1) / (pVL[mL-ix] - pVL[mL-ix-1]);
                        iv++;
                        if (t >= d) { d = t; ig = ix + 1; ih = iv - 1; }
                    } else {
                        int lcmiv1 = pIU[mU-iv+1];
                        double t = (pVL[mL-ix] - pVU[mU-iv+1]) * (double)(lcmiv - lcmiv1) / (pVU[mU-iv] - pVU[mU-iv+1])
                                 - (double)(gcmix - lcmiv1 - 1);
                        ix--;
                        if (t > d) { d = t; ig = ix + 1; ih = iv; }
                    }
                    if (ix < 1) ix = 1;
                    if (iv > ll) iv = ll;
                    if (pIL[mL-ix] == pIU[mU-iv]) break;
                }
                s_ig = ig; s_ih = ih;
                if (d < s_dip) s_done = 1;
            }
        } else {
            // ---- d-walk phase 2: parallel t evaluation (exact f64) + ordered reduce ----
            int S = s_S;
            double bd = -1e308; unsigned bm = 0;   // (ig<<17)|(ih<<2)|br1
            int s0 = tid * 32;
            if (s0 < S) {
                int ix = ckpt[tid].x, iv = ckpt[tid].y;
                int send = min(s0 + 32, S);
                for (int s = s0; s < send; s++) {
                    int gcmix = pIL[mL-ix], lcmiv = pIU[mU-iv];
                    double t; unsigned m2;
                    if (gcmix > lcmiv) {
                        int gcmi1 = pIL[mL-ix-1];
                        t = (double)(lcmiv - gcmi1 + 1)
                          - (pVU[mU-iv] - pVL[mL-ix-1]) * (double)(gcmix - gcmi1) / (pVL[mL-ix] - pVL[mL-ix-1]);
                        m2 = ((unsigned)(ix+1) << 17) | ((unsigned)iv << 2) | 1u;
                        iv++;
                    } else {
                        int lcmiv1 = pIU[mU-iv+1];
                        t = (pVL[mL-ix] - pVU[mU-iv+1]) * (double)(lcmiv - lcmiv1) / (pVU[mU-iv] - pVU[mU-iv+1])
                          - (double)(gcmix - lcmiv1 - 1);
                        m2 = ((unsigned)ix << 17) | ((unsigned)iv << 2);
                        ix--;
                    }
                    if (ix < 1) ix = 1;
                    if (iv > ll) iv = ll;
                    if (t > bd || (t == bd && (m2 & 1u))) { bd = t; bm = m2; }
                }
            }
            red[tid] = bd; meta[tid] = bm;
            __syncthreads();
            for (int s = 512; s > 0; s >>= 1) {
                if (tid < s) {
                    double dr = red[tid + s]; unsigned mr = meta[tid + s];
                    if (dr > red[tid] || (dr == red[tid] && (mr & 1u))) { red[tid] = dr; meta[tid] = mr; }
                }
                __syncthreads();
            }
            if (tid == 0) {
                double d = 0.0; int ig = lg, ih = ll;
                double dr = red[0]; unsigned mr = meta[0];
                if (dr > 0.0 || (dr == 0.0 && (mr & 1u))) {
                    d = dr; ig = (int)(mr >> 17) & 0x7fff; ih = (int)(mr >> 2) & 0x7fff;
                }
                s_ig = ig; s_ih = ih;
                if (d < s_dip) s_done = 1;
            }
            __syncthreads();
        }
        __syncthreads();
        if (s_done) break;

        // ---- fused parallel segment scans (f32) ----
        int ig = s_ig, ih = s_ih;
        float lmax = -1e30f, umax = -1e30f;

        if (lg > ig) {
            int base = mL - lg, nseg = lg - ig;
            int A = pIL[base], B = pIL[base + nseg];
            int per = (B - A + 1 + 1023) / 1024;
            int lo = A + tid * per, hi = min(lo + per - 1, B);
            if (lo <= hi) {
                int l2 = 0, h2 = nseg - 1;
                while (l2 < h2) { int mid = (l2+h2+1)>>1; if (pIL[base+mid] <= lo) l2 = mid; else h2 = mid-1; }
                int t = l2;
                int jb = pIL[base+t], je = pIL[base+t+1];
                float xjb = pFL[base+t], xje = pFL[base+t+1];
                bool valid = (je - jb > 1) && (xje != xjb);
                float C = valid ? (float)(je - jb) / (xje - xjb) : 0.0f;
                for (int i = lo; i <= hi; i++) {
                    while (i > je && t < nseg - 1) {
                        t++; jb = je; xjb = xje;
                        je = pIL[base+t+1]; xje = pFL[base+t+1];
                        valid = (je - jb > 1) && (xje != xjb);
                        C = valid ? (float)(je - jb) / (xje - xjb) : 0.0f;
                    }
                    if (valid) {
                        float tt = (float)(i - jb + 1) - (g_sorted[i-1] - xjb) * C;
                        if (tt > lmax) lmax = tt;
                    }
                }
            }
        }
        if (ll > ih) {
            int baseU = mU - ih, nseg = ll - ih;
            int A = pIU[baseU], B = pIU[baseU - nseg];
            int per = (B - A + 1 + 1023) / 1024;
            int lo = A + tid * per, hi = min(lo + per - 1, B);
            if (lo <= hi) {
                int l2 = 0, h2 = nseg - 1;
                while (l2 < h2) { int mid = (l2+h2+1)>>1; if (pIU[baseU-mid] <= lo) l2 = mid; else h2 = mid-1; }
                int t = l2;
                int jb = pIU[baseU-t], je = pIU[baseU-t-1];
                float xjb = pFU[baseU-t], xje = pFU[baseU-t-1];
                bool valid = (je - jb > 1) && (xje != xjb);
                float C = valid ? (float)(je - jb) / (xje - xjb) : 0.0f;
                for (int i = lo; i <= hi; i++) {
                    while (i > je && t < nseg - 1) {
                        t++; jb = je; xjb = xje;
                        je = pIU[baseU-t-1]; xje = pFU[baseU-t-1];
                        valid = (je - jb > 1) && (xje != xjb);
                        C = valid ? (float)(je - jb) / (xje - xjb) : 0.0f;
                    }
                    if (valid) {
                        float tt = (g_sorted[i-1] - xjb) * C - (float)(i - jb - 1);
                        if (tt > umax) umax = tt;
                    }
                }
            }
        }

        red[tid] = (double)lmax;
        __syncthreads();
        for (int s = 512; s > 0; s >>= 1) {
            if (tid < s) { double o = red[tid+s]; if (o > red[tid]) red[tid] = o; }
            __syncthreads();
        }
        double rl = red[0];
        __syncthreads();
        red[tid] = (double)umax;
        __syncthreads();
        for (int s = 512; s > 0; s >>= 1) {
            if (tid < s) { double o = red[tid+s]; if (o > red[tid]) red[tid] = o; }
            __syncthreads();
        }
        double ru = red[0];
        __syncthreads();

        if (tid == 0) {
            double dl = (lg > ig) ? ((rl > 1.0) ? rl : 1.0) : 0.0;
            double du = (ll > ih) ? ((ru > 1.0) ? ru : 1.0) : 0.0;
            double dn = (du > dl) ? du : dl;
            if (s_dip < dn) s_dip = dn;
            int nl = pIL[mL - s_ig], nh = pIU[mU - s_ih];
            if ((s_low == nl && s_high == nh) || nl >= nh) s_done = 1;
            else { s_low = nl; s_high = nh; }
        }
        __syncthreads();
        if (s_done) break;
    }
    __syncthreads();
    if (tid == 0) out[0] = (float)(s_dip / (2.0 * (double)N));
}

// ---------------------------------------------------------------------------
extern "C" void kernel_launch(void* const* d_in, const int* in_sizes, int n_in,
                              void* d_out, int out_size) {
    const float* X   = (const float*)d_in[0];
    const float* PV  = (const float*)d_in[1];
    const int*   IDX = (const int*)d_in[2];

    const int D = 128;
    int N = in_sizes[0] / D;
    if (N <= 0 || N > MAXN) return;

    float* proj = nullptr; float* sorted = nullptr; void* tmp = nullptr;
    cudaGetSymbolAddress((void**)&proj, g_proj);
    cudaGetSymbolAddress((void**)&sorted, g_sorted);
    cudaGetSymbolAddress(&tmp, g_cub_tmp);

    cudaFuncSetAttribute(k_dip,   cudaFuncAttributeMaxDynamicSharedMemorySize, DIP_DYN);
    cudaFuncSetAttribute(k_level, cudaFuncAttributeMaxDynamicSharedMemorySize, LVL2_DYN);

    k_matvec<<<(N * 32 + 255) / 256, 256>>>(X, PV, IDX, N);

    size_t tb = 0;
    cub::DeviceRadixSort::SortKeys(nullptr, tb, proj, sorted, N);
    if (tb > sizeof(g_cub_tmp)) return;
    cub::DeviceRadixSort::SortKeys(tmp, tb, proj, sorted, N);

    int nchunk = (N + CH - 1) / CH;
    int nsuper = (nchunk + SC - 1) / SC;
    int nhyper = (nsuper + HC - 1) / HC;

    int *lh_i, *uh_i, *sl_i, *su_i, *hl_i, *hu_i;
    double *lh_v, *uh_v, *sl_v, *su_v, *hl_v, *hu_v;
    int *lhn, *uhn, *sln, *sun, *hln, *hun;
    cudaGetSymbolAddress((void**)&lh_i, g_lh_idx);  cudaGetSymbolAddress((void**)&lh_v, g_lh_val);  cudaGetSymbolAddress((void**)&lhn, g_lhn);
    cudaGetSymbolAddress((void**)&uh_i, g_uh_idx);  cudaGetSymbolAddress((void**)&uh_v, g_uh_val);  cudaGetSymbolAddress((void**)&uhn, g_uhn);
    cudaGetSymbolAddress((void**)&sl_i, g_slh_idx); cudaGetSymbolAddress((void**)&sl_v, g_slh_val); cudaGetSymbolAddress((void**)&sln, g_slhn);
    cudaGetSymbolAddress((void**)&su_i, g_suh_idx); cudaGetSymbolAddress((void**)&su_v, g_suh_val); cudaGetSymbolAddress((void**)&sun, g_suhn);
    cudaGetSymbolAddress((void**)&hl_i, g_hlh_idx); cudaGetSymbolAddress((void**)&hl_v, g_hlh_val); cudaGetSymbolAddress((void**)&hln, g_hlhn);
    cudaGetSymbolAddress((void**)&hu_i, g_huh_idx); cudaGetSymbolAddress((void**)&hu_v, g_huh_val); cudaGetSymbolAddress((void**)&hun, g_huhn);

    k_chunk_hulls<<<nchunk, 128>>>(N);
    k_level<<<nsuper, 256, 4096 * 32>>>(lh_i, lh_v, lhn, sl_i, sl_v, sln,
                                        uh_i, uh_v, uhn, su_i, su_v, sun,
                                        SC, CH, SSPAN, nchunk, 4096);
    k_level<<<nhyper, 256, LVL2_DYN>>>(sl_i, sl_v, sln, hl_i, hl_v, hln,
                                       su_i, su_v, sun, hu_i, hu_v, hun,
                                       HC, SSPAN, HSPAN, nsuper, 6400);

    k_dip<<<1, 1024, DIP_DYN>>>(N, (float*)d_out);
}

// round 8
// speedup vs baseline: 1.1621x; 1.1621x over previous
#include <cuda_runtime.h>
#include <cuda_bf16.h>
#include <cub/cub.cuh>

#define CH 256
#define SC 16
#define HC 8
constexpr int MAXN = 1 << 18;
constexpr int MAXC = MAXN / CH;          // 1024
constexpr int MAXS = MAXC / SC;          // 64
constexpr int MAXH = MAXS / HC;          // 8
constexpr int CAP  = 5120;
constexpr int DIP_DYN = CAP * 32 + 4096;
constexpr int LVL_DYN_MAX = 3072 * 32;

__device__ float  g_proj[MAXN];
__device__ __align__(16) float g_sorted[MAXN];
// level 0 (chunk) hulls
__device__ int    g_lh_idx[MAXN];  __device__ double g_lh_val[MAXN];  __device__ int g_lhn[MAXC];
__device__ int    g_uh_idx[MAXN];  __device__ double g_uh_val[MAXN];  __device__ int g_uhn[MAXC];
// level 1 (super = 16 chunks)
__device__ int    g_slh_idx[MAXN]; __device__ double g_slh_val[MAXN]; __device__ int g_slhn[MAXS];
__device__ int    g_suh_idx[MAXN]; __device__ double g_suh_val[MAXN]; __device__ int g_suhn[MAXS];
// level 2 (hyper = 8 supers)
__device__ int    g_hlh_idx[MAXN]; __device__ double g_hlh_val[MAXN]; __device__ int g_hlhn[MAXH];
__device__ int    g_huh_idx[MAXN]; __device__ double g_huh_val[MAXN]; __device__ int g_huhn[MAXH];
// k_dip overflow fallback
__device__ int    g_Hidx[MAXN + 2]; __device__ double g_Hval[MAXN + 2]; __device__ float g_Hv32[MAXN + 2];
__device__ int    g_Sidx[MAXN + 2]; __device__ double g_Sval[MAXN + 2]; __device__ float g_Sv32[MAXN + 2];
__device__ unsigned char g_cub_tmp[1 << 24];

// ---------------- matvec: one warp per row, D=128 ----------------
__global__ void k_matvec(const float* __restrict__ X, const float* __restrict__ PV,
                         const int* __restrict__ IDX, int N) {
    __shared__ __align__(16) float sp[128];
    int pidx = IDX[0];
    if (threadIdx.x < 128) sp[threadIdx.x] = PV[pidx * 128 + threadIdx.x];
    __syncthreads();
    int g    = blockIdx.x * blockDim.x + threadIdx.x;
    int row  = g >> 5;
    int lane = g & 31;
    if (row >= N) return;
    const float4* xr = reinterpret_cast<const float4*>(X) + (size_t)row * 32;
    float4 a = xr[lane];
    float4 b = reinterpret_cast<const float4*>(sp)[lane];
    float s = a.x * b.x + a.y * b.y + a.z * b.z + a.w * b.w;
#pragma unroll
    for (int o = 16; o; o >>= 1) s += __shfl_xor_sync(0xffffffffu, s, o);
    if (lane == 0) g_proj[row] = s;
}

// ---------------- strict monotone-chain merges ----------------
// Reference pop rule: break iff (cv-bv)*(bi-ai) < (bv-av)*(ci-bi)  [f64].
// f32-filtered: decide in f32 outside a provably safe margin, exact f64 otherwise.
__device__ __forceinline__ int merge_f32(int* idx, double* val, float* v32, int n) {
    int m = 0, ai = 0, bi = 0; double av = 0.0, bv = 0.0; float af = 0.f, bf = 0.f;
    for (int r = 0; r < n; r++) {
        int ci = idx[r]; double cv = val[r]; float cf = v32[r];
        while (m >= 2) {
            float p1 = (cf - bf) * (float)(bi - ai);
            float p2 = (bf - af) * (float)(ci - bi);
            float eps = 4e-7f * (fabsf(p1) + fabsf(p2)) + 1e-33f;
            bool brk;
            float diff = p1 - p2;
            if (diff < -eps) brk = true;
            else if (diff > eps) brk = false;
            else brk = ((cv - bv) * (double)(bi - ai)) < ((bv - av) * (double)(ci - bi));
            if (brk) break;
            m--; bi = ai; bv = av; bf = af;
            if (m >= 2) { ai = idx[m - 2]; av = val[m - 2]; af = v32[m - 2]; }
        }
        idx[m] = ci; val[m] = cv; v32[m] = cf;
        ai = bi; av = bv; af = bf; bi = ci; bv = cv; bf = cf; m++;
    }
    return m;
}
__device__ __forceinline__ int merge_f64(int* idx, double* val, int n) {
    int m = 0, ai = 0, bi = 0; double av = 0.0, bv = 0.0;
    for (int r = 0; r < n; r++) {
        int ci = idx[r]; double cv = val[r];
        while (m >= 2) {
            if ((cv - bv) * (double)(bi - ai) < (bv - av) * (double)(ci - bi)) break;
            m--; bi = ai; bv = av;
            if (m >= 2) { ai = idx[m - 2]; av = val[m - 2]; }
        }
        idx[m] = ci; val[m] = cv;
        ai = bi; av = bv; bi = ci; bv = cv; m++;
    }
    return m;
}

// ---------------- level 0: per-chunk strict hulls ----------------
__global__ void k_chunk_hulls(int N) {
    __shared__ int    iL[CH]; __shared__ double vL[CH]; __shared__ float fL[CH];
    __shared__ int    iU[CH]; __shared__ double vU[CH]; __shared__ float fU[CH];
    __shared__ int smL, smU;
    int c = blockIdx.x, tid = threadIdx.x;
    int s = c * CH + 1;
    int e = min((c + 1) * CH, N);
    int n = e - s + 1;
    for (int k = tid; k < n; k += blockDim.x) {
        float x = g_sorted[s + k - 1];
        iL[k] = s + k;            vL[k] = (double)x;            fL[k] = x;
        iU[n - 1 - k] = s + k;    vU[n - 1 - k] = (double)x;    fU[n - 1 - k] = x;
    }
    __syncthreads();
    if (tid == 0)  smL = merge_f32(iL, vL, fL, n);
    if (tid == 64) smU = merge_f32(iU, vU, fU, n);
    __syncthreads();
    int base = c * CH;
    for (int k = tid; k < smL; k += blockDim.x) { g_lh_idx[base + k] = iL[k]; g_lh_val[base + k] = vL[k]; }
    for (int k = tid; k < smU; k += blockDim.x) { g_uh_idx[base + k] = iU[k]; g_uh_val[base + k] = vU[k]; }
    if (tid == 0)  g_lhn[c] = smL;
    if (tid == 64) g_uhn[c] = smU;
}

// ---------------- generic level merge ----------------
__global__ void k_level(const int* sLi, const double* sLv, const int* sLn,
                        int* dLi, double* dLv, int* dLn,
                        const int* sUi, const double* sUv, const int* sUn,
                        int* dUi, double* dUv, int* dUn,
                        int group, int srcStride, int dstStride, int nsrc, int cap) {
    extern __shared__ unsigned char sm[];
    double* vL = (double*)sm;
    double* vU = vL + cap;
    float*  fL = (float*)(vU + cap);
    float*  fU = fL + cap;
    int*    iL = (int*)(fU + cap);
    int*    iU = iL + cap;
    __shared__ int offL[24], offU[24];
    __shared__ int totL, totU, mL, mU, fbL, fbU;
    int b = blockIdx.x, tid = threadIdx.x;
    int j0 = b * group, j1 = min(j0 + group, nsrc), nj = j1 - j0;
    if (tid == 0)  { int o = 0; for (int j = j0; j < j1; j++) { offL[j-j0] = o; o += sLn[j]; } totL = o; fbL = (o > cap); }
    if (tid == 32) { int o = 0; for (int j = j1-1; j >= j0; j--) { offU[j1-1-j] = o; o += sUn[j]; } totU = o; fbU = (o > cap); }
    __syncthreads();
    size_t db = (size_t)b * dstStride;
    for (int j = 0; j < nj; j++) {
        int src = (j0+j)*srcStride, len = sLn[j0+j], dst = offL[j];
        if (!fbL) for (int k = tid; k < len; k += blockDim.x) { iL[dst+k] = sLi[src+k]; double v = sLv[src+k]; vL[dst+k] = v; fL[dst+k] = (float)v; }
        else      for (int k = tid; k < len; k += blockDim.x) { dLi[db+dst+k] = sLi[src+k]; dLv[db+dst+k] = sLv[src+k]; }
        int ju = j1-1-j, srcu = ju*srcStride, lenu = sUn[ju], dstu = offU[j];
        if (!fbU) for (int k = tid; k < lenu; k += blockDim.x) { iU[dstu+k] = sUi[srcu+k]; double v = sUv[srcu+k]; vU[dstu+k] = v; fU[dstu+k] = (float)v; }
        else      for (int k = tid; k < lenu; k += blockDim.x) { dUi[db+dstu+k] = sUi[srcu+k]; dUv[db+dstu+k] = sUv[srcu+k]; }
    }
    __syncthreads();
    if (tid == 0)  mL = fbL ? merge_f64(dLi+db, dLv+db, totL) : merge_f32(iL, vL, fL, totL);
    if (tid == 32) mU = fbU ? merge_f64(dUi+db, dUv+db, totU) : merge_f32(iU, vU, fU, totU);
    __syncthreads();
    if (!fbL) for (int k = tid; k < mL; k += blockDim.x) { dLi[db+k] = iL[k]; dLv[db+k] = vL[k]; }
    if (!fbU) for (int k = tid; k < mU; k += blockDim.x) { dUi[db+k] = iU[k]; dUv[db+k] = vU[k]; }
    if (tid == 0)  dLn[b] = mL;
    if (tid == 32) dUn[b] = mU;
}

__device__ __forceinline__ float block_maxf(float v, float* red, int tid) {
    red[tid] = v;
    __syncthreads();
    for (int s = 512; s > 0; s >>= 1) {
        if (tid < s) { float o = red[tid + s]; if (o > red[tid]) red[tid] = o; }
        __syncthreads();
    }
    float r = red[0];
    __syncthreads();
    return r;
}

__global__ void __launch_bounds__(1024, 1) k_dip(int N, int nchunk, int nsuper, int nhyper, float* out) {
    extern __shared__ unsigned char dyn[];
    double* dValL = (double*)dyn;                  // CAP
    double* dValU = dValL + CAP;                   // CAP
    float*  dF32L = (float*)(dValU + CAP);         // CAP
    float*  dF32U = dF32L + CAP;                   // CAP
    float*  red   = dF32U + CAP;                   // 1024
    int*    dIdxL = (int*)(red + 1024);            // CAP
    int*    dIdxU = dIdxL + CAP;                   // CAP

    __shared__ int s_low, s_high, s_done;
    __shared__ double s_dip;
    __shared__ int nsL, nsU, totL, totU, s_mL, s_mU, s_lg, s_ll, s_ig, s_ih;
    __shared__ int4 srcL[40], srcU[40];
    __shared__ int* pIL; __shared__ double* pVL; __shared__ float* pFL;
    __shared__ int* pIU; __shared__ double* pVU; __shared__ float* pFU;

    int tid = threadIdx.x;
    if (tid == 0) { s_low = 1; s_high = N; s_dip = 1.0; s_done = 0; }
    __syncthreads();
    if (N < 4 || g_sorted[0] == g_sorted[N - 1]) {
        if (tid == 0) out[0] = (float)(1.0 / (2.0 * (double)(N > 0 ? N : 1)));
        return;
    }

    for (int iter = 0; iter < 64; iter++) {
        int low = s_low, high = s_high;

        // -------- source lists --------
        if (tid == 0) {
            int hc = (high - 1) / CH;
            int nH = hc / (HC * SC);
            int nS = hc / SC;
            int ns = 0, o = 0;
            for (int h = 0; h < nH; h++)        { int l = g_hlhn[h]; srcL[ns] = make_int4(6, h * HC * SC * CH, l, o); ns++; o += l; }
            for (int s = nH * HC; s < nS; s++)  { int l = g_slhn[s]; srcL[ns] = make_int4(1, s * SC * CH, l, o); ns++; o += l; }
            for (int c = nS * SC; c < hc; c++)  { int l = g_lhn[c];  srcL[ns] = make_int4(0, c * CH, l, o); ns++; o += l; }
            int rb = hc * CH + 1, rl = high - hc * CH;
            srcL[ns] = make_int4(2, rb, rl, o); ns++; o += rl;
            nsL = ns; totL = o;
            bool fb = (o > CAP);
            pIL = fb ? g_Hidx : dIdxL; pVL = fb ? g_Hval : dValL; pFL = fb ? g_Hv32 : dF32L;
        }
        if (tid == 32) {
            int lc = (low - 1) / CH;
            int cfirst = lc + 1;
            int sS = (cfirst + SC - 1) / SC;
            int hH = (cfirst + HC * SC - 1) / (HC * SC);
            int send = min(hH * HC, nsuper);
            int cend = min(sS * SC, nchunk);
            int ns = 0, o = 0;
            for (int h = nhyper - 1; h >= hH; h--)   { int l = g_huhn[h]; srcU[ns] = make_int4(7, h * HC * SC * CH, l, o); ns++; o += l; }
            for (int s = send - 1; s >= sS; s--)     { int l = g_suhn[s]; srcU[ns] = make_int4(4, s * SC * CH, l, o); ns++; o += l; }
            for (int c = cend - 1; c >= cfirst; c--) { int l = g_uhn[c];  srcU[ns] = make_int4(3, c * CH, l, o); ns++; o += l; }
            int rb = min(cfirst * CH, N), rl = rb - low + 1;
            srcU[ns] = make_int4(5, rb, rl, o); ns++; o += rl;
            nsU = ns; totU = o;
            bool fb = (o > CAP);
            pIU = fb ? g_Sidx : dIdxU; pVU = fb ? g_Sval : dValU; pFU = fb ? g_Sv32 : dF32U;
        }
        __syncthreads();

        // -------- stage candidates --------
        {
            int* IL = pIL; double* VL = pVL; float* FL = pFL;
            for (int j = 0; j < nsL; j++) {
                int4 sd = srcL[j];
                if (sd.x == 2) {
                    for (int k = tid; k < sd.z; k += 1024) {
                        float x = g_sorted[sd.y + k - 1];
                        IL[sd.w + k] = sd.y + k; VL[sd.w + k] = (double)x; FL[sd.w + k] = x;
                    }
                } else {
                    const int* si; const double* sv;
                    if (sd.x == 0)      { si = g_lh_idx;  sv = g_lh_val; }
                    else if (sd.x == 1) { si = g_slh_idx; sv = g_slh_val; }
                    else                { si = g_hlh_idx; sv = g_hlh_val; }
                    for (int k = tid; k < sd.z; k += 1024) {
                        double v = sv[sd.y + k];
                        IL[sd.w + k] = si[sd.y + k]; VL[sd.w + k] = v; FL[sd.w + k] = (float)v;
                    }
                }
            }
            int* IU = pIU; double* VU = pVU; float* FU = pFU;
            for (int j = 0; j < nsU; j++) {
                int4 sd = srcU[j];
                if (sd.x == 5) {
                    for (int k = tid; k < sd.z; k += 1024) {
                        float x = g_sorted[sd.y - k - 1];
                        IU[sd.w + k] = sd.y - k; VU[sd.w + k] = (double)x; FU[sd.w + k] = x;
                    }
                } else {
                    const int* si; const double* sv;
                    if (sd.x == 3)      { si = g_uh_idx;  sv = g_uh_val; }
                    else if (sd.x == 4) { si = g_suh_idx; sv = g_suh_val; }
                    else                { si = g_huh_idx; sv = g_huh_val; }
                    for (int k = tid; k < sd.z; k += 1024) {
                        double v = sv[sd.y + k];
                        IU[sd.w + k] = si[sd.y + k]; VU[sd.w + k] = v; FU[sd.w + k] = (float)v;
                    }
                }
            }
        }
        __syncthreads();

        // -------- merges + chain truncation --------
        if (tid == 0) {
            int m = merge_f32(pIL, pVL, pFL, totL);
            int lo2 = 0, hi2 = m - 1;
            while (lo2 < hi2) { int mid = (lo2 + hi2 + 1) >> 1; if (pIL[mid] <= low) lo2 = mid; else hi2 = mid - 1; }
            s_mL = m; s_lg = m - lo2;
        }
        if (tid == 32) {
            int m = merge_f32(pIU, pVU, pFU, totU);
            int lo2 = 0, hi2 = m - 1;
            while (lo2 < hi2) { int mid = (lo2 + hi2 + 1) >> 1; if (pIU[mid] >= high) lo2 = mid; else hi2 = mid - 1; }
            s_mU = m; s_ll = m - lo2;
        }
        __syncthreads();

        int mL = s_mL, mU = s_mU, lg = s_lg, ll = s_ll;
        // mapping: gcm[i] = pIL[mL - i] (i=1..lg), lcm[i] = pIU[mU - i] (i=1..ll)

        // -------- d-walk (verbatim reference port, f64) --------
        if (tid == 0) {
            int ig = lg, ih = ll, ix = lg - 1, iv = 2;
            double d = 0.0;
            if (!(lg == 2 && ll == 2)) {
                long long guard = 4LL * N + 16;
                while (guard-- > 0) {
                    int gcmix = pIL[mL - ix], lcmiv = pIU[mU - iv];
                    if (gcmix > lcmiv) {
                        int gcmi1 = pIL[mL - ix - 1];
                        double xg = pVL[mL - ix], xg1 = pVL[mL - ix - 1], xl = pVU[mU - iv];
                        double t = (double)(lcmiv - gcmi1 + 1) - (xl - xg1) * (double)(gcmix - gcmi1) / (xg - xg1);
                        iv++;
                        if (t >= d) { d = t; ig = ix + 1; ih = iv - 1; }
                    } else {
                        int lcmiv1 = pIU[mU - iv + 1];
                        double xg = pVL[mL - ix], xl = pVU[mU - iv], xl1 = pVU[mU - iv + 1];
                        double t = (xg - xl1) * (double)(lcmiv - lcmiv1) / (xl - xl1) - (double)(gcmix - lcmiv1 - 1);
                        ix--;
                        if (t > d) { d = t; ig = ix + 1; ih = iv; }
                    }
                    if (ix < 1) ix = 1;
                    if (iv > ll) iv = ll;
                    if (pIL[mL - ix] == pIU[mU - iv]) break;
                }
            } else d = 1.0;
            s_ig = ig; s_ih = ih;
            if (d < s_dip) s_done = 1;
        }
        __syncthreads();
        if (s_done) break;

        // -------- fused parallel segment scans, f32, float4-vectorized --------
        int ig = s_ig, ih = s_ih;
        float lmax = -1e30f, umax = -1e30f;

        if (lg > ig) {   // covers [gcm[lg], gcm[ig]]
            int base = mL - lg;
            int nseg = lg - ig;
            int A = pIL[base], B = pIL[base + nseg];
            int total = B - A + 1;
            int per = (total + 1023) / 1024;
            int lo = A + tid * per;
            int hi = min(lo + per - 1, B);
            if (lo <= hi) {
                int lo2 = 0, hi2 = nseg - 1;
                while (lo2 < hi2) { int mid = (lo2 + hi2 + 1) >> 1; if (pIL[base + mid] <= lo) lo2 = mid; else hi2 = mid - 1; }
                int t = lo2;
                int jb = pIL[base + t], je = pIL[base + t + 1];
                float xjb = pFL[base + t], xje = pFL[base + t + 1];
                bool valid = (je - jb > 1) && (xje != xjb);
                float C = valid ? (float)(je - jb) / (xje - xjb) : 0.0f;

                int i = lo;
                // scalar head to 4-alignment of (i-1)
                for (; i <= hi && ((i - 1) & 3); i++) {
                    while (i > je && t < nseg - 1) {
                        t++; jb = je; xjb = xje;
                        je = pIL[base + t + 1]; xje = pFL[base + t + 1];
                        valid = (je - jb > 1) && (xje != xjb);
                        C = valid ? (float)(je - jb) / (xje - xjb) : 0.0f;
                    }
                    if (valid) { float tt = (float)(i - jb + 1) - (g_sorted[i - 1] - xjb) * C; if (tt > lmax) lmax = tt; }
                }
                // 16-wide tiles: 4 independent float4 loads (MLP=4)
                for (; i + 15 <= hi; i += 16) {
                    const float4* p = reinterpret_cast<const float4*>(g_sorted + (i - 1));
                    float4 v0 = p[0], v1 = p[1], v2 = p[2], v3 = p[3];
                    float xv[16] = {v0.x, v0.y, v0.z, v0.w, v1.x, v1.y, v1.z, v1.w,
                                    v2.x, v2.y, v2.z, v2.w, v3.x, v3.y, v3.z, v3.w};
#pragma unroll
                    for (int q = 0; q < 16; q++) {
                        int ii = i + q;
                        while (ii > je && t < nseg - 1) {
                            t++; jb = je; xjb = xje;
                            je = pIL[base + t + 1]; xje = pFL[base + t + 1];
                            valid = (je - jb > 1) && (xje != xjb);
                            C = valid ? (float)(je - jb) / (xje - xjb) : 0.0f;
                        }
                        if (valid) { float tt = (float)(ii - jb + 1) - (xv[q] - xjb) * C; if (tt > lmax) lmax = tt; }
                    }
                }
                // scalar tail
                for (; i <= hi; i++) {
                    while (i > je && t < nseg - 1) {
                        t++; jb = je; xjb = xje;
                        je = pIL[base + t + 1]; xje = pFL[base + t + 1];
                        valid = (je - jb > 1) && (xje != xjb);
                        C = valid ? (float)(je - jb) / (xje - xjb) : 0.0f;
                    }
                    if (valid) { float tt = (float)(i - jb + 1) - (g_sorted[i - 1] - xjb) * C; if (tt > lmax) lmax = tt; }
                }
            }
        }
        if (ll > ih) {   // covers [lcm[ih], lcm[ll]]
            int baseU = mU - ih;
            int nseg = ll - ih;
            int A = pIU[baseU], B = pIU[baseU - nseg];
            int total = B - A + 1;
            int per = (total + 1023) / 1024;
            int lo = A + tid * per;
            int hi = min(lo + per - 1, B);
            if (lo <= hi) {
                int lo2 = 0, hi2 = nseg - 1;
                while (lo2 < hi2) { int mid = (lo2 + hi2 + 1) >> 1; if (pIU[baseU - mid] <= lo) lo2 = mid; else hi2 = mid - 1; }
                int t = lo2;
                int jb = pIU[baseU - t], je = pIU[baseU - t - 1];
                float xjb = pFU[baseU - t], xje = pFU[baseU - t - 1];
                bool valid = (je - jb > 1) && (xje != xjb);
                float C = valid ? (float)(je - jb) / (xje - xjb) : 0.0f;

                int i = lo;
                for (; i <= hi && ((i - 1) & 3); i++) {
                    while (i > je && t < nseg - 1) {
                        t++; jb = je; xjb = xje;
                        je = pIU[baseU - t - 1]; xje = pFU[baseU - t - 1];
                        valid = (je - jb > 1) && (xje != xjb);
                        C = valid ? (float)(je - jb) / (xje - xjb) : 0.0f;
                    }
                    if (valid) { float tt = (g_sorted[i - 1] - xjb) * C - (float)(i - jb - 1); if (tt > umax) umax = tt; }
                }
                for (; i + 15 <= hi; i += 16) {
                    const float4* p = reinterpret_cast<const float4*>(g_sorted + (i - 1));
                    float4 v0 = p[0], v1 = p[1], v2 = p[2], v3 = p[3];
                    float xv[16] = {v0.x, v0.y, v0.z, v0.w, v1.x, v1.y, v1.z, v1.w,
                                    v2.x, v2.y, v2.z, v2.w, v3.x, v3.y, v3.z, v3.w};
#pragma unroll
                    for (int q = 0; q < 16; q++) {
                        int ii = i + q;
                        while (ii > je && t < nseg - 1) {
                            t++; jb = je; xjb = xje;
                            je = pIU[baseU - t - 1]; xje = pFU[baseU - t - 1];
                            valid = (je - jb > 1) && (xje != xjb);
                            C = valid ? (float)(je - jb) / (xje - xjb) : 0.0f;
                        }
                        if (valid) { float tt = (xv[q] - xjb) * C - (float)(ii - jb - 1); if (tt > umax) umax = tt; }
                    }
                }
                for (; i <= hi; i++) {
                    while (i > je && t < nseg - 1) {
                        t++; jb = je; xjb = xje;
                        je = pIU[baseU - t - 1]; xje = pFU[baseU - t - 1];
                        valid = (je - jb > 1) && (xje != xjb);
                        C = valid ? (float)(je - jb) / (xje - xjb) : 0.0f;
                    }
                    if (valid) { float tt = (g_sorted[i - 1] - xjb) * C - (float)(i - jb - 1); if (tt > umax) umax = tt; }
                }
            }
        }

        float rl = block_maxf(lmax, red, tid);
        float ru = block_maxf(umax, red, tid);

        if (tid == 0) {
            double dl = (lg > ig) ? (((double)rl > 1.0) ? (double)rl : 1.0) : 0.0;
            double du = (ll > ih) ? (((double)ru > 1.0) ? (double)ru : 1.0) : 0.0;
            double dn = (du > dl) ? du : dl;
            if (s_dip < dn) s_dip = dn;
            int nl = pIL[mL - s_ig], nh = pIU[mU - s_ih];
            if ((s_low == nl && s_high == nh) || nl >= nh) s_done = 1;
            else { s_low = nl; s_high = nh; }
        }
        __syncthreads();
        if (s_done) break;
    }
    __syncthreads();
    if (tid == 0) out[0] = (float)(s_dip / (2.0 * (double)N));
}

// ---------------------------------------------------------------------------
extern "C" void kernel_launch(void* const* d_in, const int* in_sizes, int n_in,
                              void* d_out, int out_size) {
    const float* X   = (const float*)d_in[0];
    const float* PV  = (const float*)d_in[1];
    const int*   IDX = (const int*)d_in[2];

    const int D = 128;
    int N = in_sizes[0] / D;
    if (N <= 0 || N > MAXN) return;

    float* proj = nullptr; float* sorted = nullptr; void* tmp = nullptr;
    cudaGetSymbolAddress((void**)&proj, g_proj);
    cudaGetSymbolAddress((void**)&sorted, g_sorted);
    cudaGetSymbolAddress(&tmp, g_cub_tmp);

    cudaFuncSetAttribute(k_dip,   cudaFuncAttributeMaxDynamicSharedMemorySize, DIP_DYN);
    cudaFuncSetAttribute(k_level, cudaFuncAttributeMaxDynamicSharedMemorySize, LVL_DYN_MAX);

    k_matvec<<<(N * 32 + 255) / 256, 256>>>(X, PV, IDX, N);

    size_t tb = 0;
    cub::DeviceRadixSort::SortKeys(nullptr, tb, proj, sorted, N);
    if (tb > sizeof(g_cub_tmp)) return;
    cub::DeviceRadixSort::SortKeys(tmp, tb, proj, sorted, N);

    int nchunk = (N + CH - 1) / CH;
    int nsuper = (nchunk + SC - 1) / SC;
    int nhyper = (nsuper + HC - 1) / HC;

    int *lh_i, *uh_i, *sl_i, *su_i, *hl_i, *hu_i;
    double *lh_v, *uh_v, *sl_v, *su_v, *hl_v, *hu_v;
    int *lhn, *uhn, *sln, *sun, *hln, *hun;
    cudaGetSymbolAddress((void**)&lh_i, g_lh_idx);  cudaGetSymbolAddress((void**)&lh_v, g_lh_val);  cudaGetSymbolAddress((void**)&lhn, g_lhn);
    cudaGetSymbolAddress((void**)&uh_i, g_uh_idx);  cudaGetSymbolAddress((void**)&uh_v, g_uh_val);  cudaGetSymbolAddress((void**)&uhn, g_uhn);
    cudaGetSymbolAddress((void**)&sl_i, g_slh_idx); cudaGetSymbolAddress((void**)&sl_v, g_slh_val); cudaGetSymbolAddress((void**)&sln, g_slhn);
    cudaGetSymbolAddress((void**)&su_i, g_suh_idx); cudaGetSymbolAddress((void**)&su_v, g_suh_val); cudaGetSymbolAddress((void**)&sun, g_suhn);
    cudaGetSymbolAddress((void**)&hl_i, g_hlh_idx); cudaGetSymbolAddress((void**)&hl_v, g_hlh_val); cudaGetSymbolAddress((void**)&hln, g_hlhn);
    cudaGetSymbolAddress((void**)&hu_i, g_huh_idx); cudaGetSymbolAddress((void**)&hu_v, g_huh_val); cudaGetSymbolAddress((void**)&hun, g_huhn);

    k_chunk_hulls<<<nchunk, 128>>>(N);
    k_level<<<nsuper, 256, 2048 * 32>>>(lh_i, lh_v, lhn, sl_i, sl_v, sln,
                                        uh_i, uh_v, uhn, su_i, su_v, sun,
                                        SC, CH, SC * CH, nchunk, 2048);
    k_level<<<nhyper, 256, 3072 * 32>>>(sl_i, sl_v, sln, hl_i, hl_v, hln,
                                        su_i, su_v, sun, hu_i, hu_v, hun,
                                        HC, SC * CH, HC * SC * CH, nsuper, 3072);

    k_dip<<<1, 1024, DIP_DYN>>>(N, nchunk, nsuper, nhyper, (float*)d_out);
}